// round 2
// baseline (speedup 1.0000x reference)
#include <cuda_runtime.h>
#include <cuda_bf16.h>
#include <mma.h>

using namespace nvcuda;

// ---------------------------------------------------------------- constants
constexpr int MTOK = 8192;            // Bt*S
constexpr int DIN  = 4096;
constexpr int DOUT = 4096;
constexpr int E = 8, DK = 32, R = 16;
constexpr int NPROJ = 2 * E * DK + E * R;  // 640
constexpr int KBASE = 3 * DIN;             // 12288  (hi,lo,hi split panels)
constexpr int GCOLS = 160;                 // 128 lora + 1 bias + 31 pad
constexpr int KEXT  = 512;                 // 3*160 + 32 pad
constexpr int KP    = KBASE + KEXT;        // 12800

// ---------------------------------------------------------------- scratch
__device__ __align__(256) __nv_bfloat16 g_Xp[(size_t)MTOK * KP];   // packed activations
__device__ __align__(256) __nv_bfloat16 g_Wp[(size_t)DOUT * KP];   // packed W + B2 ext
__device__ __align__(256) __nv_bfloat16 g_Pp[(size_t)NPROJ * KBASE]; // packed [Wq;Wk;A]
__device__ __align__(256) float         g_P [(size_t)MTOK * NPROJ];  // projections (fp32)

__device__ __forceinline__ void split2(float v, __nv_bfloat16& hi, __nv_bfloat16& lo) {
    hi = __float2bfloat16(v);
    lo = __float2bfloat16(v - __bfloat162float(hi));
}

// ------------------------------------------------- pack x -> [hi | lo | hi]
__global__ void split_x_kernel(const float* __restrict__ x) {
    size_t idx = (size_t)blockIdx.x * 256 + threadIdx.x;
    if (idx >= (size_t)MTOK * DIN) return;
    int row = (int)(idx / DIN), col = (int)(idx % DIN);
    __nv_bfloat16 hi, lo; split2(x[idx], hi, lo);
    __nv_bfloat16* d = g_Xp + (size_t)row * KP;
    d[col] = hi; d[DIN + col] = lo; d[2 * DIN + col] = hi;
}

// ------------------------------------------------- pack W -> [hi | hi | lo]
__global__ void split_w_kernel(const float* __restrict__ W) {
    size_t idx = (size_t)blockIdx.x * 256 + threadIdx.x;
    if (idx >= (size_t)DOUT * DIN) return;
    int row = (int)(idx / DIN), col = (int)(idx % DIN);
    __nv_bfloat16 hi, lo; split2(W[idx], hi, lo);
    __nv_bfloat16* d = g_Wp + (size_t)row * KP;
    d[col] = hi; d[DIN + col] = hi; d[2 * DIN + col] = lo;
}

// ------------------------------ pack [Wq(256); Wk(256); A(128)] -> [hi|hi|lo]
__global__ void split_proj_kernel(const float* __restrict__ Wq,
                                  const float* __restrict__ Wk,
                                  const float* __restrict__ A) {
    size_t idx = (size_t)blockIdx.x * 256 + threadIdx.x;
    if (idx >= (size_t)NPROJ * DIN) return;
    int row = (int)(idx / DIN), col = (int)(idx % DIN);
    float v;
    if (row < 256)      v = Wq[(size_t)row * DIN + col];
    else if (row < 512) v = Wk[(size_t)(row - 256) * DIN + col];
    else                v = A [(size_t)(row - 512) * DIN + col];
    __nv_bfloat16 hi, lo; split2(v, hi, lo);
    __nv_bfloat16* d = g_Pp + (size_t)row * KBASE;
    d[col] = hi; d[DIN + col] = hi; d[2 * DIN + col] = lo;
}

// --------------- pack B2 extension cols of Wp: [B2_hi | B2_hi | B2_lo | 0]
// B2[o, j]: j<128 -> Bm[e=j/16, o, r=j%16]; j==128 -> b[o]; j in [129,160) -> 0
__global__ void pack_b2_kernel(const float* __restrict__ Bm, const float* __restrict__ b) {
    int idx = blockIdx.x * 256 + threadIdx.x;
    if (idx >= DOUT * KEXT) return;
    int o = idx / KEXT, jj = idx - o * KEXT;
    int jb = (jj < GCOLS) ? jj : (jj < 2 * GCOLS) ? jj - GCOLS : (jj < 3 * GCOLS) ? jj - 2 * GCOLS : -1;
    float v = 0.f;
    if (jb >= 0) {
        if (jb < E * R) {
            int e = jb >> 4, r = jb & 15;
            v = Bm[((size_t)e * DOUT + o) * R + r];
        } else if (jb == E * R) {
            v = b[o];
        }
    }
    __nv_bfloat16 hi, lo; split2(v, hi, lo);
    __nv_bfloat16 outv = (jj < 2 * GCOLS) ? hi : (jj < 3 * GCOLS) ? lo : __float2bfloat16(0.f);
    g_Wp[(size_t)o * KP + KBASE + jj] = outv;
}

// ------------------- routing: softmax over experts, write G ext cols of Xp
// G[t, j]: j<128 -> w_e * h[t,e,r] (e=j/16, r=j%16); j==128 -> 1; else 0
// panels: [G_hi | G_lo | G_hi | 0]. One warp per token; lane == d (DK==32).
__global__ void routing_kernel() {
    int warp = (blockIdx.x * blockDim.x + threadIdx.x) >> 5;
    int lane = threadIdx.x & 31;
    if (warp >= MTOK) return;
    const float* Pt = g_P + (size_t)warp * NPROJ;
    float s[E];
#pragma unroll
    for (int e = 0; e < E; e++) {
        float p = Pt[e * DK + lane] * Pt[E * DK + e * DK + lane];
#pragma unroll
        for (int o = 16; o > 0; o >>= 1) p += __shfl_xor_sync(0xffffffffu, p, o);
        s[e] = p * 0.17677669529663687f;   // 1/sqrt(32)
    }
    float m = s[0];
#pragma unroll
    for (int e = 1; e < E; e++) m = fmaxf(m, s[e]);
    float Z = 0.f;
#pragma unroll
    for (int e = 0; e < E; e++) { s[e] = __expf(s[e] - m); Z += s[e]; }
    float inv = 1.f / Z;

    __nv_bfloat16* Gt = g_Xp + (size_t)warp * KP + KBASE;
#pragma unroll
    for (int j = lane; j < KEXT; j += 32) {
        int jb = (j < GCOLS) ? j : (j < 2 * GCOLS) ? j - GCOLS : (j < 3 * GCOLS) ? j - 2 * GCOLS : -1;
        float g = 0.f;
        if (jb >= 0) {
            if (jb < E * R)       g = s[jb >> 4] * inv * Pt[2 * E * DK + jb];
            else if (jb == E * R) g = 1.0f;   // bias column (SCALING == 1)
        }
        __nv_bfloat16 hi, lo; split2(g, hi, lo);
        __nv_bfloat16 outv = (j < GCOLS) ? hi : (j < 2 * GCOLS) ? lo
                           : (j < 3 * GCOLS) ? hi : __float2bfloat16(0.f);
        Gt[j] = outv;
    }
}

// --------------------------------------------------------- bf16 WMMA GEMM
// C[M,N] = A[M,K] @ B[N,K]^T, 128x128x64 tiles, 8 warps, warp tile 64x32.
// MODE 0: A=g_Xp (ld KP), B=g_Pp (ld KBASE), C=g_P (ld NPROJ), K=KBASE
// MODE 1: A=g_Xp (ld KP), B=g_Wp (ld KP),   C=param (ld DOUT), K=KP
constexpr int BM = 128, BN = 128, BK = 64, SST = 72;

template <int MODE>
__global__ void __launch_bounds__(256) gemm_bf16_kernel(float* __restrict__ Cparam) {
    const __nv_bfloat16* __restrict__ Ag = g_Xp;
    const __nv_bfloat16* __restrict__ Bg = (MODE == 0) ? g_Pp : g_Wp;
    float* __restrict__ Cg = (MODE == 0) ? g_P : Cparam;
    const int lda = KP;
    const int ldb = (MODE == 0) ? KBASE : KP;
    const int ldc = (MODE == 0) ? NPROJ : DOUT;
    const int K   = (MODE == 0) ? KBASE : KP;

    __shared__ __align__(16) __nv_bfloat16 Xs[BM * SST];
    __shared__ __align__(16) __nv_bfloat16 Ws[BN * SST];

    const int rowBase = blockIdx.y * BM;
    const int colBase = blockIdx.x * BN;
    const int tid = threadIdx.x;
    const int warpId = tid >> 5;
    const int wr = warpId >> 2;   // 0..1
    const int wc = warpId & 3;    // 0..3

    wmma::fragment<wmma::accumulator, 16, 16, 16, float> acc[4][2];
#pragma unroll
    for (int i = 0; i < 4; i++)
#pragma unroll
        for (int j = 0; j < 2; j++) wmma::fill_fragment(acc[i][j], 0.f);

    for (int kb = 0; kb < K; kb += BK) {
        __syncthreads();
#pragma unroll
        for (int p = 0; p < 4; p++) {
            int q = tid + p * 256;      // 0..1023
            int r = q >> 3;             // 0..127
            int c = (q & 7) * 8;        // 0..56 (8 bf16 = 16B)
            *reinterpret_cast<uint4*>(&Xs[r * SST + c]) =
                *reinterpret_cast<const uint4*>(&Ag[(size_t)(rowBase + r) * lda + kb + c]);
            *reinterpret_cast<uint4*>(&Ws[r * SST + c]) =
                *reinterpret_cast<const uint4*>(&Bg[(size_t)(colBase + r) * ldb + kb + c]);
        }
        __syncthreads();
#pragma unroll
        for (int kk = 0; kk < BK; kk += 16) {
            wmma::fragment<wmma::matrix_a, 16, 16, 16, __nv_bfloat16, wmma::row_major> af[4];
            wmma::fragment<wmma::matrix_b, 16, 16, 16, __nv_bfloat16, wmma::col_major> bf[2];
#pragma unroll
            for (int i = 0; i < 4; i++)
                wmma::load_matrix_sync(af[i], &Xs[(wr * 64 + i * 16) * SST + kk], SST);
#pragma unroll
            for (int j = 0; j < 2; j++)
                wmma::load_matrix_sync(bf[j], &Ws[(wc * 32 + j * 16) * SST + kk], SST);
#pragma unroll
            for (int i = 0; i < 4; i++)
#pragma unroll
                for (int j = 0; j < 2; j++)
                    wmma::mma_sync(acc[i][j], af[i], bf[j], acc[i][j]);
        }
    }

#pragma unroll
    for (int i = 0; i < 4; i++)
#pragma unroll
        for (int j = 0; j < 2; j++) {
            float* cptr = &Cg[(size_t)(rowBase + wr * 64 + i * 16) * ldc + colBase + wc * 32 + j * 16];
            wmma::store_matrix_sync(cptr, acc[i][j], ldc, wmma::mem_row_major);
        }
}

// -------------------------------------------------------------------- launch
// Inputs (metadata order): x, W, b, Wq, Wk, A, Bm
extern "C" void kernel_launch(void* const* d_in, const int* in_sizes, int n_in,
                              void* d_out, int out_size) {
    const float* x  = (const float*)d_in[0];
    const float* W  = (const float*)d_in[1];
    const float* b  = (const float*)d_in[2];
    const float* Wq = (const float*)d_in[3];
    const float* Wk = (const float*)d_in[4];
    const float* A  = (const float*)d_in[5];
    const float* Bm = (const float*)d_in[6];
    float* out = (float*)d_out;

    split_x_kernel   <<<(MTOK * DIN + 255) / 256, 256>>>(x);
    split_w_kernel   <<<(DOUT * DIN + 255) / 256, 256>>>(W);
    split_proj_kernel<<<(NPROJ * DIN + 255) / 256, 256>>>(Wq, Wk, A);
    pack_b2_kernel   <<<(DOUT * KEXT + 255) / 256, 256>>>(Bm, b);

    // projections P = x @ [Wq;Wk;A]^T  (split-bf16, K = 12288)
    gemm_bf16_kernel<0><<<dim3(NPROJ / BN, MTOK / BM), 256>>>(nullptr);

    // routing -> G extension columns of Xp
    routing_kernel<<<(MTOK * 32) / 256, 256>>>();

    // out = x @ W^T + G @ B2^T (+bias), one flat K = 12800 bf16 GEMM
    gemm_bf16_kernel<1><<<dim3(DOUT / BN, MTOK / BM), 256>>>(out);
}

// round 4
// speedup vs baseline: 4.1623x; 4.1623x over previous
#include <cuda_runtime.h>
#include <cuda_bf16.h>
#include <cstdint>

// ---------------------------------------------------------------- constants
constexpr int MTOK = 8192, DIN = 4096, DOUT = 4096;
constexpr int E = 8, DK = 32, R = 16;
constexpr int NPROJ = 640, NPROJ_PAD = 768;
constexpr int KBASE = 3 * DIN;            // 12288 (hi|lo|hi split panels)
constexpr int GCOLS = 160;                // 128 lora + 1 bias + 31 pad
constexpr int KEXT  = 512;                // 3*160 + 32 pad
constexpr int KP    = KBASE + KEXT;       // 12800

// GEMM tiling (cg2 pair computes 256x256 tile)
constexpr int TM = 256, TN = 256, BK = 64, NST = 4;
constexpr int STAGE_BYTES = 2 * 128 * 128;           // A 16KB + B 16KB
constexpr int SMEM_DATA0  = 1024;
constexpr int SMEM_BYTES  = SMEM_DATA0 + NST * STAGE_BYTES;   // 132096
constexpr uint32_t IDESC = (1u<<4) | (1u<<7) | (1u<<10) | ((TN/8)<<17) | ((TM/16)<<24);

// ---------------------------------------------------------------- scratch
__device__ __align__(1024) __nv_bfloat16 g_Xp[(size_t)MTOK * KP];
__device__ __align__(1024) __nv_bfloat16 g_Wp[(size_t)DOUT * KP];
__device__ __align__(1024) __nv_bfloat16 g_Pp[(size_t)NPROJ_PAD * DIN];
__device__ __align__(1024) float         g_P [(size_t)MTOK * NPROJ_PAD];

// ---------------------------------------------------------------- ptx utils
__device__ __forceinline__ uint32_t smem_u32(const void* p) {
    uint32_t a;
    asm("{ .reg .u64 t; cvta.to.shared.u64 t, %1; cvt.u32.u64 %0, t; }" : "=r"(a) : "l"(p));
    return a;
}
__device__ __forceinline__ uint32_t ctarank() {
    uint32_t r; asm("mov.u32 %0, %%cluster_ctarank;" : "=r"(r)); return r;
}
__device__ __forceinline__ void cluster_sync() {
    asm volatile("barrier.cluster.arrive.aligned;" ::: "memory");
    asm volatile("barrier.cluster.wait.aligned;" ::: "memory");
}
__device__ __forceinline__ void mbar_init(uint32_t a, uint32_t c) {
    asm volatile("mbarrier.init.shared.b64 [%0], %1;" :: "r"(a), "r"(c) : "memory");
}
__device__ __forceinline__ void mbar_inval(uint32_t a) {
    asm volatile("mbarrier.inval.shared.b64 [%0];" :: "r"(a) : "memory");
}
__device__ __forceinline__ void mbar_arrive_rank0(uint32_t a) {
    asm volatile("{ .reg .b32 ra; mapa.shared::cluster.u32 ra, %0, 0;"
                 " mbarrier.arrive.shared::cluster.b64 _, [ra]; }" :: "r"(a) : "memory");
}
__device__ __forceinline__ void mbar_wait(uint32_t a, uint32_t parity) {
    asm volatile("{ .reg .pred P;\n"
                 "W%=: mbarrier.try_wait.parity.acquire.cta.shared::cta.b64 P, [%0], %1, 0x989680;\n"
                 "@P bra D%=;\n bra W%=;\nD%=: }"
                 :: "r"(a), "r"(parity) : "memory");
}
__device__ __forceinline__ void cpa16(uint32_t s, const void* g) {
    asm volatile("cp.async.cg.shared.global [%0], [%1], 16;" :: "r"(s), "l"(g));
}
__device__ __forceinline__ void cp_commit() { asm volatile("cp.async.commit_group;"); }
template <int N> __device__ __forceinline__ void cp_wait() {
    asm volatile("cp.async.wait_group %0;" :: "n"(N));
}
__device__ __forceinline__ void fence_async() {
    asm volatile("fence.proxy.async.shared::cta;" ::: "memory");
}
// SW128 K-major descriptor (LBO=1, SBO=64), Blackwell version bit
constexpr uint64_t DESC_BASE = (2ull<<61) | (1ull<<46) | (64ull<<32) | (1ull<<16);
__device__ __forceinline__ uint64_t mk_desc(uint32_t a) { return DESC_BASE | ((a >> 4) & 0x3FFF); }

// ---------------------------------------------------------------- pack kernels
__device__ __forceinline__ void split2(float v, __nv_bfloat16& hi, __nv_bfloat16& lo) {
    hi = __float2bfloat16(v);
    lo = __float2bfloat16(v - __bfloat162float(hi));
}

__global__ void split_x_kernel(const float* __restrict__ x) {
    size_t idx = (size_t)blockIdx.x * 256 + threadIdx.x;
    if (idx >= (size_t)MTOK * DIN) return;
    int row = (int)(idx / DIN), col = (int)(idx % DIN);
    __nv_bfloat16 hi, lo; split2(x[idx], hi, lo);
    __nv_bfloat16* d = g_Xp + (size_t)row * KP;
    d[col] = hi; d[DIN + col] = lo; d[2 * DIN + col] = hi;
}

__global__ void split_w_kernel(const float* __restrict__ W) {
    size_t idx = (size_t)blockIdx.x * 256 + threadIdx.x;
    if (idx >= (size_t)DOUT * DIN) return;
    int row = (int)(idx / DIN), col = (int)(idx % DIN);
    __nv_bfloat16 hi, lo; split2(W[idx], hi, lo);
    __nv_bfloat16* d = g_Wp + (size_t)row * KP;
    d[col] = hi; d[DIN + col] = hi; d[2 * DIN + col] = lo;
}

__global__ void split_proj_kernel(const float* __restrict__ Wq,
                                  const float* __restrict__ Wk,
                                  const float* __restrict__ A) {
    size_t idx = (size_t)blockIdx.x * 256 + threadIdx.x;
    if (idx >= (size_t)NPROJ_PAD * DIN) return;
    int row = (int)(idx / DIN), col = (int)(idx % DIN);
    float v = 0.f;
    if (row < 256)      v = Wq[(size_t)row * DIN + col];
    else if (row < 512) v = Wk[(size_t)(row - 256) * DIN + col];
    else if (row < 640) v = A [(size_t)(row - 512) * DIN + col];
    g_Pp[idx] = __float2bfloat16(v);
}

__global__ void pack_b2_kernel(const float* __restrict__ Bm, const float* __restrict__ b) {
    int idx = blockIdx.x * 256 + threadIdx.x;
    if (idx >= DOUT * KEXT) return;
    int o = idx / KEXT, jj = idx - o * KEXT;
    int jb = (jj < GCOLS) ? jj : (jj < 2*GCOLS) ? jj - GCOLS : (jj < 3*GCOLS) ? jj - 2*GCOLS : -1;
    float v = 0.f;
    if (jb >= 0) {
        if (jb < E * R) { int e = jb >> 4, r = jb & 15; v = Bm[((size_t)e * DOUT + o) * R + r]; }
        else if (jb == E * R) v = b[o];
    }
    __nv_bfloat16 hi, lo; split2(v, hi, lo);
    __nv_bfloat16 outv = (jj < 2*GCOLS) ? hi : (jj < 3*GCOLS) ? lo : __float2bfloat16(0.f);
    g_Wp[(size_t)o * KP + KBASE + jj] = outv;
}

// ---------------------------------------------------------------- routing
__global__ void routing_kernel() {
    int warp = (blockIdx.x * blockDim.x + threadIdx.x) >> 5;
    int lane = threadIdx.x & 31;
    if (warp >= MTOK) return;
    const float* Pt = g_P + (size_t)warp * NPROJ_PAD;
    float s[E];
#pragma unroll
    for (int e = 0; e < E; e++) {
        float p = Pt[e * DK + lane] * Pt[E * DK + e * DK + lane];
#pragma unroll
        for (int o = 16; o > 0; o >>= 1) p += __shfl_xor_sync(0xffffffffu, p, o);
        s[e] = p * 0.17677669529663687f;
    }
    float m = s[0];
#pragma unroll
    for (int e = 1; e < E; e++) m = fmaxf(m, s[e]);
    float Z = 0.f;
#pragma unroll
    for (int e = 0; e < E; e++) { s[e] = __expf(s[e] - m); Z += s[e]; }
    float inv = 1.f / Z;

    __nv_bfloat16* Gt = g_Xp + (size_t)warp * KP + KBASE;
#pragma unroll
    for (int j = lane; j < KEXT; j += 32) {
        int jb = (j < GCOLS) ? j : (j < 2*GCOLS) ? j - GCOLS : (j < 3*GCOLS) ? j - 2*GCOLS : -1;
        float g = 0.f;
        if (jb >= 0) {
            if (jb < E * R)       g = s[jb >> 4] * inv * Pt[2 * E * DK + jb];
            else if (jb == E * R) g = 1.0f;
        }
        __nv_bfloat16 hi, lo; split2(g, hi, lo);
        Gt[j] = (j < GCOLS) ? hi : (j < 2*GCOLS) ? lo : (j < 3*GCOLS) ? hi : __float2bfloat16(0.f);
    }
}

// ---------------------------------------------------------------- tcgen05 GEMM
// MODE 0: A=g_Xp (lda KP, first 4096 cols), B=g_Pp (ld DIN),  C=g_P (ld 768), K=DIN
// MODE 1: A=g_Xp (lda KP),                  B=g_Wp (ld KP),   C=out (ld DOUT), K=KP
// NOTE: entire body guarded by __CUDA_ARCH_FEAT_SM103_ALL — the compute_103
// (family) compilation pass must contain no tcgen05/cta_group::2 PTX.
template <int MODE>
__global__ void __cluster_dims__(2, 1, 1) __launch_bounds__(256, 1)
gemm_cg2_kernel(float* __restrict__ Cparam) {
#if defined(__CUDA_ARCH_FEAT_SM103_ALL)
    constexpr int LDA = KP;
    constexpr int LDB = (MODE == 0) ? DIN : KP;
    constexpr int LDC = (MODE == 0) ? NPROJ_PAD : DOUT;
    constexpr int NCH = ((MODE == 0) ? DIN : KP) / BK;

    const __nv_bfloat16* __restrict__ Ag = g_Xp;
    const __nv_bfloat16* __restrict__ Bg = (MODE == 0) ? g_Pp : g_Wp;
    float* __restrict__ Cg = (MODE == 0) ? g_P : Cparam;

    extern __shared__ char smem[];
    const uint32_t sbase = smem_u32(smem);
    const int tid = threadIdx.x, wid = tid >> 5, lane = tid & 31;
    const uint32_t rank = ctarank();
    const int n_tile = blockIdx.x >> 1;
    const int m_tile = blockIdx.y;

    const uint32_t FULL0 = sbase + 8;    // 4 x 8B, count=2
    const uint32_t MMAB0 = sbase + 40;   // 4 x 8B, count=1

    if (tid == 0) {
#pragma unroll
        for (int s = 0; s < NST; s++) { mbar_init(FULL0 + s * 8, 2); mbar_init(MMAB0 + s * 8, 1); }
    }
    if (wid == 0)
        asm volatile("tcgen05.alloc.cta_group::2.sync.aligned.shared::cta.b32 [%0], %1;"
                     :: "r"(sbase), "r"(512) : "memory");
    __syncthreads();
    uint32_t tmem;
    asm volatile("ld.shared.b32 %0, [%1];" : "=r"(tmem) : "r"(sbase));
    cluster_sync();   // mbarriers visible cluster-wide before any cluster arrive/commit

    const __nv_bfloat16* Arow = Ag + (size_t)(m_tile * TM + rank * 128) * LDA;
    const __nv_bfloat16* Brow = Bg + (size_t)(n_tile * TN + rank * 128) * LDB;

    auto fill = [&](int chunk) {
        const int kb = chunk * BK;
        const uint32_t sa = sbase + SMEM_DATA0 + (chunk & (NST - 1)) * STAGE_BYTES;
        const uint32_t sb = sa + 16384;
#pragma unroll
        for (int q0 = 0; q0 < 1024; q0 += 256) {
            int q = q0 + tid;
            int r = q >> 3, c = q & 7;
            uint32_t off = (uint32_t)(r * 128 + c * 16);
            uint32_t sw = off ^ ((off >> 3) & 0x70);
            cpa16(sa + sw, Arow + (size_t)r * LDA + kb + c * 8);
            cpa16(sb + sw, Brow + (size_t)r * LDB + kb + c * 8);
        }
        cp_commit();
    };

    uint32_t fphase[NST] = {0, 0, 0, 0};
    uint32_t mphase[NST] = {0, 0, 0, 0};

    fill(0); fill(1); fill(2);

    for (int i = 0; i < NCH; i++) {
        const int s = i & (NST - 1);
        // chunk i's cp.async group complete (per-thread), then CTA-wide
        const int rem = NCH - 1 - i;
        if (rem >= 2) cp_wait<2>(); else if (rem == 1) cp_wait<1>(); else cp_wait<0>();
        __syncthreads();
        if (tid == 0) {
            fence_async();                    // publish SMEM to async proxy
            mbar_arrive_rank0(FULL0 + s * 8); // both ranks arrive on leader's bar
        }
        if (rank == 0 && tid == 0) {
            mbar_wait(FULL0 + s * 8, fphase[s]); fphase[s] ^= 1;
            uint64_t ad = mk_desc(sbase + SMEM_DATA0 + s * STAGE_BYTES);
            uint64_t bd = mk_desc(sbase + SMEM_DATA0 + s * STAGE_BYTES + 16384);
#pragma unroll
            for (int kk = 0; kk < 4; kk++) {
                uint32_t en = ((i > 0) || (kk > 0)) ? 1u : 0u;
                uint64_t adk = ad + kk * 2, bdk = bd + kk * 2;
                asm volatile("{ .reg .pred p; setp.ne.u32 p, %5, 0;\n"
                             "tcgen05.mma.cta_group::2.kind::f16 [%0], %1, %2, %3,"
                             " {%4,%4,%4,%4,%4,%4,%4,%4}, p; }"
                             :: "r"(tmem), "l"(adk), "l"(bdk), "r"(IDESC), "r"(0u), "r"(en)
                             : "memory");
            }
            asm volatile("tcgen05.commit.cta_group::2.mbarrier::arrive::one.shared::cluster.multicast::cluster.b64 [%0], %1;"
                         :: "r"(MMAB0 + s * 8), "h"((uint16_t)3) : "memory");
        }
        const int j = i + NST - 1;
        if (j < NCH) {
            const int s2 = j & (NST - 1);
            if (j >= NST) { mbar_wait(MMAB0 + s2 * 8, mphase[s2]); mphase[s2] ^= 1; }
            fill(j);
        }
    }

    // wait final MMA (commit covers all prior MMAs)
    const int slast = (NCH - 1) & (NST - 1);
    mbar_wait(MMAB0 + slast * 8, mphase[slast]);
    asm volatile("tcgen05.fence::after_thread_sync;" ::: "memory");

    // epilogue: warp w -> rows (w&3)*32+lane, col half (w>>2)*128
    {
        const int gm = m_tile * TM + (int)rank * 128 + (wid & 3) * 32 + lane;
        float* crow = Cg + (size_t)gm * LDC + n_tile * TN + (wid >> 2) * 128;
        const uint32_t cbase0 = tmem + (uint32_t)((wid >> 2) * 128);
#pragma unroll
        for (int cb = 0; cb < 128; cb += 32) {
            uint32_t d[32];
            asm volatile("tcgen05.ld.sync.aligned.32x32b.x32.b32 "
                "{%0,%1,%2,%3,%4,%5,%6,%7,%8,%9,%10,%11,%12,%13,%14,%15,"
                "%16,%17,%18,%19,%20,%21,%22,%23,%24,%25,%26,%27,%28,%29,%30,%31}, [%32];"
                : "=r"(d[0]),"=r"(d[1]),"=r"(d[2]),"=r"(d[3]),"=r"(d[4]),"=r"(d[5]),"=r"(d[6]),"=r"(d[7]),
                  "=r"(d[8]),"=r"(d[9]),"=r"(d[10]),"=r"(d[11]),"=r"(d[12]),"=r"(d[13]),"=r"(d[14]),"=r"(d[15]),
                  "=r"(d[16]),"=r"(d[17]),"=r"(d[18]),"=r"(d[19]),"=r"(d[20]),"=r"(d[21]),"=r"(d[22]),"=r"(d[23]),
                  "=r"(d[24]),"=r"(d[25]),"=r"(d[26]),"=r"(d[27]),"=r"(d[28]),"=r"(d[29]),"=r"(d[30]),"=r"(d[31])
                : "r"(cbase0 + cb));
            asm volatile("tcgen05.wait::ld.sync.aligned;" ::: "memory");
#pragma unroll
            for (int c = 0; c < 32; c += 4) {
                float4 v = make_float4(__uint_as_float(d[c]), __uint_as_float(d[c + 1]),
                                       __uint_as_float(d[c + 2]), __uint_as_float(d[c + 3]));
                *reinterpret_cast<float4*>(crow + cb + c) = v;
            }
        }
    }

    __syncthreads();
    if (tid == 0) {
#pragma unroll
        for (int s = 0; s < NST; s++) { mbar_inval(FULL0 + s * 8); mbar_inval(MMAB0 + s * 8); }
    }
    __syncthreads();
    if (wid == 0) {
        asm volatile("tcgen05.relinquish_alloc_permit.cta_group::2.sync.aligned;");
        asm volatile("tcgen05.dealloc.cta_group::2.sync.aligned.b32 %0, %1;" :: "r"(tmem), "r"(512));
    }
    cluster_sync();
#endif  // __CUDA_ARCH_FEAT_SM103_ALL
}

// ---------------------------------------------------------------- launch
// Inputs (metadata order): x, W, b, Wq, Wk, A, Bm
extern "C" void kernel_launch(void* const* d_in, const int* in_sizes, int n_in,
                              void* d_out, int out_size) {
    const float* x  = (const float*)d_in[0];
    const float* W  = (const float*)d_in[1];
    const float* b  = (const float*)d_in[2];
    const float* Wq = (const float*)d_in[3];
    const float* Wk = (const float*)d_in[4];
    const float* A  = (const float*)d_in[5];
    const float* Bm = (const float*)d_in[6];
    float* out = (float*)d_out;

    cudaFuncSetAttribute(gemm_cg2_kernel<0>, cudaFuncAttributeMaxDynamicSharedMemorySize, SMEM_BYTES);
    cudaFuncSetAttribute(gemm_cg2_kernel<1>, cudaFuncAttributeMaxDynamicSharedMemorySize, SMEM_BYTES);

    split_x_kernel   <<<(int)(((size_t)MTOK * DIN + 255) / 256), 256>>>(x);
    split_w_kernel   <<<(int)(((size_t)DOUT * DIN + 255) / 256), 256>>>(W);
    split_proj_kernel<<<(int)(((size_t)NPROJ_PAD * DIN + 255) / 256), 256>>>(Wq, Wk, A);
    pack_b2_kernel   <<<(DOUT * KEXT + 255) / 256, 256>>>(Bm, b);

    // projections P = x_hi @ [Wq;Wk;A]_hi^T  (single-panel bf16, K=4096)
    gemm_cg2_kernel<0><<<dim3(2 * (NPROJ_PAD / TN), MTOK / TM), 256, SMEM_BYTES>>>(nullptr);

    // routing -> G extension columns of Xp
    routing_kernel<<<(MTOK * 32) / 256, 256>>>();

    // out = x @ W^T + G @ B2^T (+bias): flat K = 12800 split-bf16 GEMM
    gemm_cg2_kernel<1><<<dim3(2 * (DOUT / TN), MTOK / TM), 256, SMEM_BYTES>>>(out);
}